// round 14
// baseline (speedup 1.0000x reference)
#include <cuda_runtime.h>
#include <cuda_bf16.h>

#define N_NODES 250000
#define N_EDGES 5000000
#define NN4 (N_NODES / 4)    // 62,500

#define BINS      16
#define BIN_SHIFT 14
#define BIN_NODES 16384      // nodes per bin (last bin: 4240)
#define BIN_CAP   393216     // edge capacity per bin (mean 327.7k, sigma ~550)
#define CPB       9          // blocks per bin in binned passes (grid = 144)
#define PCHUNK    2048       // edges per permute block (256 thr x 8)

// Scratch (device globals — no allocation allowed).
// g_deg is zero at process start (BSS) and re-zeroed at the end of every
// kernel_launch by k_node_c, so each call sees zeros. Deterministic.
__device__ int2   g_perm[BINS * BIN_CAP];  // edges grouped by col-bin (~50MB)
__device__ int    g_cursor[BINS];          // per-bin fill cursors
__device__ int    g_deg[N_NODES];
__device__ float  g_dinv[N_NODES];
__device__ float  g_y[N_NODES];      // x[i] * dinv[i]
__device__ float  g_s1[N_NODES];     // layer-1 scatter accumulator
__device__ float2 g_t[N_NODES];      // per-node layer-2 message (z * dinv)
__device__ float2 g_oacc[N_NODES];   // layer-2 scatter accumulator
__device__ float2 g_Apos, g_Aneg;    // collapsed MLP coefficients (b1 == 0)
__device__ int    g_b1zero;

__device__ __forceinline__ void red_f32(float* p, float v) {
    asm volatile("red.global.add.f32 [%0], %1;" :: "l"(p), "f"(v) : "memory");
}
__device__ __forceinline__ void red_v2f32(float2* p, float2 v) {
    asm volatile("red.global.add.v2.f32 [%0], {%1, %2};"
                 :: "l"(p), "f"(v.x), "f"(v.y) : "memory");
}

// Prep: reset bin cursors; collapse MLP if b1 == 0: z(s) = s*(s>0?A+:A-)
__global__ void k_prep(const float* __restrict__ W1,
                       const float* __restrict__ b1,
                       const float* __restrict__ W2) {
    int t = threadIdx.x;
    if (t < BINS) g_cursor[t] = 0;
    if (t != 0) return;
    float2 ap = make_float2(0.f, 0.f), an = make_float2(0.f, 0.f);
    int bz = 1;
    #pragma unroll
    for (int j = 0; j < 16; j++) {
        if (b1[j] != 0.f) bz = 0;
        float w = W1[j];
        float2 w2 = make_float2(W2[2 * j], W2[2 * j + 1]);
        if (w > 0.f) { ap.x = fmaf(w, w2.x, ap.x); ap.y = fmaf(w, w2.y, ap.y); }
        else if (w < 0.f) { an.x = fmaf(w, w2.x, an.x); an.y = fmaf(w, w2.y, an.y); }
    }
    g_Apos = ap; g_Aneg = an; g_b1zero = bz;
}

// Permute edges into col-bins. Block handles PCHUNK consecutive edges.
__global__ void __launch_bounds__(256) k_permute(const int* __restrict__ row,
                                                 const int* __restrict__ col) {
    __shared__ int h[BINS], base_[BINS], lc[BINS];
    int tid = threadIdx.x;
    if (tid < BINS) { h[tid] = 0; lc[tid] = 0; }
    __syncthreads();

    long long start = (long long)blockIdx.x * PCHUNK;
    int r[8], c[8], b[8];
    bool ok[8];
    #pragma unroll
    for (int k = 0; k < 8; k++) {
        long long e = start + k * 256 + tid;
        ok[k] = (e < N_EDGES);
        if (ok[k]) {
            r[k] = row[e];
            c[k] = col[e];
            b[k] = c[k] >> BIN_SHIFT;
            atomicAdd(&h[b[k]], 1);
        }
    }
    __syncthreads();
    if (tid < BINS) base_[tid] = atomicAdd(&g_cursor[tid], h[tid]);
    __syncthreads();
    #pragma unroll
    for (int k = 0; k < 8; k++) {
        if (ok[k]) {
            int rank = atomicAdd(&lc[b[k]], 1);
            g_perm[b[k] * BIN_CAP + base_[b[k]] + rank] = make_int2(r[k], c[k]);
        }
    }
}

// Binned degree pass: smem int histogram per bin-chunk, coalesced RED flush.
__global__ void __launch_bounds__(256) k_deg_bin() {
    extern __shared__ int iacc[];
    int tid = threadIdx.x;
    int bin = blockIdx.x / CPB, sub = blockIdx.x % CPB;
    int count = g_cursor[bin];
    for (int i = tid; i < BIN_NODES; i += 256) iacc[i] = 0;
    __syncthreads();
    int lo = (int)((long long)count * sub / CPB);
    int hi = (int)((long long)count * (sub + 1) / CPB);
    const int2* p = g_perm + bin * BIN_CAP;
    for (int i = lo + tid; i < hi; i += 256) {
        int2 e = p[i];
        atomicAdd(&iacc[e.y & (BIN_NODES - 1)], 1);
    }
    __syncthreads();
    int nbase = bin << BIN_SHIFT;
    int nb = min(BIN_NODES, N_NODES - nbase);
    for (int i = tid; i < nb; i += 256) {
        int v = iacc[i];
        if (v) atomicAdd(&g_deg[nbase + i], v);
    }
}

// Per-node (x4): dinv = rsqrt(indeg+1); y = x*dinv; s1 init with self-loop y.
__global__ void __launch_bounds__(256) k_node_a(const float* __restrict__ x) {
    int i = blockIdx.x * blockDim.x + threadIdx.x;
    if (i >= NN4) return;
    int4   d4 = ((const int4*)g_deg)[i];
    float4 x4 = ((const float4*)x)[i];
    float4 dv, y4;
    dv.x = rsqrtf((float)(d4.x + 1));
    dv.y = rsqrtf((float)(d4.y + 1));
    dv.z = rsqrtf((float)(d4.z + 1));
    dv.w = rsqrtf((float)(d4.w + 1));
    y4.x = x4.x * dv.x; y4.y = x4.y * dv.y;
    y4.z = x4.z * dv.z; y4.w = x4.w * dv.w;
    ((float4*)g_dinv)[i] = dv;
    ((float4*)g_y)[i]    = y4;
    ((float4*)g_s1)[i]   = y4;   // self-loop; final *dinv[c] in k_node_b
}

// Binned layer-1 scatter: smem float accumulator, coalesced RED flush.
__global__ void __launch_bounds__(256) k_pass2_bin() {
    extern __shared__ float facc[];
    int tid = threadIdx.x;
    int bin = blockIdx.x / CPB, sub = blockIdx.x % CPB;
    int count = g_cursor[bin];
    for (int i = tid; i < BIN_NODES; i += 256) facc[i] = 0.f;
    __syncthreads();
    int lo = (int)((long long)count * sub / CPB);
    int hi = (int)((long long)count * (sub + 1) / CPB);
    const int2* p = g_perm + bin * BIN_CAP;
    int i = lo + tid;
    // 2-wide software pipeline for gather MLP
    for (; i + 256 < hi; i += 512) {
        int2 e0 = p[i], e1 = p[i + 256];
        float y0 = g_y[e0.x];
        float y1 = g_y[e1.x];
        atomicAdd(&facc[e0.y & (BIN_NODES - 1)], y0);
        atomicAdd(&facc[e1.y & (BIN_NODES - 1)], y1);
    }
    if (i < hi) {
        int2 e = p[i];
        atomicAdd(&facc[e.y & (BIN_NODES - 1)], g_y[e.x]);
    }
    __syncthreads();
    int nbase = bin << BIN_SHIFT;
    int nb = min(BIN_NODES, N_NODES - nbase);
    for (int j = tid; j < nb; j += 256) {
        float v = facc[j];
        if (v != 0.f) red_f32(&g_s1[nbase + j], v);
    }
}

// Per-node MLP (x4 nodes/thread). Fast path when b1==0: z = s*(s>0?A+:A-).
__global__ void __launch_bounds__(256) k_node_b(const float* __restrict__ W1,
                                                const float* __restrict__ b1,
                                                const float* __restrict__ W2) {
    int i = blockIdx.x * blockDim.x + threadIdx.x;
    if (i >= NN4) return;
    float4 dv4 = ((const float4*)g_dinv)[i];
    float4 s14 = ((const float4*)g_s1)[i];

    float dv[4] = {dv4.x, dv4.y, dv4.z, dv4.w};
    float sv[4] = {dv4.x * s14.x, dv4.y * s14.y, dv4.z * s14.z, dv4.w * s14.w};
    float2 tv[4];

    if (g_b1zero) {
        float2 ap = g_Apos, an = g_Aneg;
        #pragma unroll
        for (int q = 0; q < 4; q++) {
            float s = sv[q];
            float2 A = (s > 0.f) ? ap : an;
            float sd = s * dv[q];
            tv[q] = make_float2(sd * A.x, sd * A.y);
        }
    } else {
        #pragma unroll
        for (int q = 0; q < 4; q++) {
            float s = sv[q];
            float z0 = 0.f, z1 = 0.f;
            #pragma unroll
            for (int j = 0; j < 16; j++) {
                float h = fmaxf(fmaf(W1[j], s, b1[j]), 0.f);
                z0 = fmaf(h, W2[2 * j], z0);
                z1 = fmaf(h, W2[2 * j + 1], z1);
            }
            tv[q] = make_float2(z0 * dv[q], z1 * dv[q]);
        }
    }
    float4 lo = make_float4(tv[0].x, tv[0].y, tv[1].x, tv[1].y);
    float4 hi = make_float4(tv[2].x, tv[2].y, tv[3].x, tv[3].y);
    ((float4*)g_t)[2 * i]        = lo;
    ((float4*)g_t)[2 * i + 1]    = hi;
    ((float4*)g_oacc)[2 * i]     = lo;
    ((float4*)g_oacc)[2 * i + 1] = hi;
}

// Binned layer-2 scatter: two smem float accumulators, v2 RED flush.
__global__ void __launch_bounds__(256) k_pass3_bin() {
    extern __shared__ float sacc[];
    float* ax = sacc;
    float* ay = sacc + BIN_NODES;
    int tid = threadIdx.x;
    int bin = blockIdx.x / CPB, sub = blockIdx.x % CPB;
    int count = g_cursor[bin];
    for (int i = tid; i < BIN_NODES; i += 256) { ax[i] = 0.f; ay[i] = 0.f; }
    __syncthreads();
    int lo = (int)((long long)count * sub / CPB);
    int hi = (int)((long long)count * (sub + 1) / CPB);
    const int2* p = g_perm + bin * BIN_CAP;
    int i = lo + tid;
    for (; i + 256 < hi; i += 512) {
        int2 e0 = p[i], e1 = p[i + 256];
        float2 t0 = g_t[e0.x];
        float2 t1 = g_t[e1.x];
        int l0 = e0.y & (BIN_NODES - 1), l1 = e1.y & (BIN_NODES - 1);
        atomicAdd(&ax[l0], t0.x);
        atomicAdd(&ay[l0], t0.y);
        atomicAdd(&ax[l1], t1.x);
        atomicAdd(&ay[l1], t1.y);
    }
    if (i < hi) {
        int2 e = p[i];
        float2 t = g_t[e.x];
        int l = e.y & (BIN_NODES - 1);
        atomicAdd(&ax[l], t.x);
        atomicAdd(&ay[l], t.y);
    }
    __syncthreads();
    int nbase = bin << BIN_SHIFT;
    int nb = min(BIN_NODES, N_NODES - nbase);
    for (int j = tid; j < nb; j += 256) {
        float vx = ax[j], vy = ay[j];
        if (vx != 0.f || vy != 0.f)
            red_v2f32(&g_oacc[nbase + j], make_float2(vx, vy));
    }
}

// Final: scale by dinv, add b2, 2-way softmax (2 nodes/thread via float4).
// Also re-zeroes g_deg for the next call (deterministic across replays).
__global__ void __launch_bounds__(256) k_node_c(const float* __restrict__ b2,
                                                float* __restrict__ out) {
    int i = blockIdx.x * blockDim.x + threadIdx.x;   // pair index
    if (i >= N_NODES / 2) return;
    float bb0 = b2[0], bb1 = b2[1];
    float2 dv = ((const float2*)g_dinv)[i];
    float4 a  = ((const float4*)g_oacc)[i];
    float4 o;
    {
        float o0 = fmaf(dv.x, a.x, bb0);
        float o1 = fmaf(dv.x, a.y, bb1);
        float m = fmaxf(o0, o1);
        float e0 = __expf(o0 - m), e1 = __expf(o1 - m);
        float inv = __frcp_rn(e0 + e1);
        o.x = e0 * inv; o.y = e1 * inv;
    }
    {
        float o0 = fmaf(dv.y, a.z, bb0);
        float o1 = fmaf(dv.y, a.w, bb1);
        float m = fmaxf(o0, o1);
        float e0 = __expf(o0 - m), e1 = __expf(o1 - m);
        float inv = __frcp_rn(e0 + e1);
        o.z = e0 * inv; o.w = e1 * inv;
    }
    ((float4*)out)[i] = o;
    ((int2*)g_deg)[i] = make_int2(0, 0);   // zero for next call
}

extern "C" void kernel_launch(void* const* d_in, const int* in_sizes, int n_in,
                              void* d_out, int out_size) {
    const float* x   = (const float*)d_in[0];
    const int*   row = (const int*)d_in[1];            // [2, N_EDGES] int32
    const int*   col = row + N_EDGES;
    const float* W1  = (const float*)d_in[2];
    const float* b1  = (const float*)d_in[3];
    const float* W2  = (const float*)d_in[4];
    const float* b2  = (const float*)d_in[5];
    float* out = (float*)d_out;

    static int attr_done = 0;
    if (!attr_done) {
        cudaFuncSetAttribute(k_deg_bin,
            cudaFuncAttributeMaxDynamicSharedMemorySize, BIN_NODES * 4);
        cudaFuncSetAttribute(k_pass2_bin,
            cudaFuncAttributeMaxDynamicSharedMemorySize, BIN_NODES * 4);
        cudaFuncSetAttribute(k_pass3_bin,
            cudaFuncAttributeMaxDynamicSharedMemorySize, BIN_NODES * 8);
        attr_done = 1;
    }

    const int BT = 256;
    const int node4Grid = (NN4 + BT - 1) / BT;
    const int pairGrid  = (N_NODES / 2 + BT - 1) / BT;
    const int permGrid  = (N_EDGES + PCHUNK - 1) / PCHUNK;
    const int binGrid   = BINS * CPB;

    k_prep<<<1, 32>>>(W1, b1, W2);
    k_permute<<<permGrid, BT>>>(row, col);
    k_deg_bin<<<binGrid, BT, BIN_NODES * 4>>>();
    k_node_a<<<node4Grid, BT>>>(x);
    k_pass2_bin<<<binGrid, BT, BIN_NODES * 4>>>();
    k_node_b<<<node4Grid, BT>>>(W1, b1, W2);
    k_pass3_bin<<<binGrid, BT, BIN_NODES * 8>>>();
    k_node_c<<<pairGrid, BT>>>(b2, out);
}

// round 15
// speedup vs baseline: 1.1332x; 1.1332x over previous
#include <cuda_runtime.h>
#include <cuda_bf16.h>

#define N_NODES 250000
#define N_EDGES 5000000
#define E8 (N_EDGES / 8)     // 625,000 threads for edge kernels
#define NN4 (N_NODES / 4)    // 62,500

// Scratch (device globals — no allocation allowed).
// g_deg is zero at process start (BSS) and re-zeroed at the end of every
// kernel_launch by k_node_c, so each call sees zeros. Deterministic.
__device__ int    g_deg[N_NODES];
__device__ float  g_dinv[N_NODES];
__device__ float  g_y[N_NODES];      // x[i] * dinv[i]
__device__ float  g_s1[N_NODES];     // layer-1 scatter accumulator
__device__ float2 g_t[N_NODES];      // per-node layer-2 message (z * dinv)
__device__ float2 g_oacc[N_NODES];   // layer-2 scatter accumulator

__device__ __forceinline__ void red_f32(float* p, float v) {
    asm volatile("red.global.add.f32 [%0], %1;" :: "l"(p), "f"(v) : "memory");
}
__device__ __forceinline__ void red_v2f32(float2* p, float2 v) {
    asm volatile("red.global.add.v2.f32 [%0], {%1, %2};"
                 :: "l"(p), "f"(v.x), "f"(v.y) : "memory");
}

// Degree pass: count in-degree from col (8 edges/thread, int32 indices)
__global__ void __launch_bounds__(256) k_edge_deg(const int* __restrict__ col) {
    int idx = blockIdx.x * blockDim.x + threadIdx.x;
    if (idx >= E8) return;
    const int4* c4 = (const int4*)col;
    int4 a = c4[2 * idx], b = c4[2 * idx + 1];
    atomicAdd(&g_deg[a.x], 1);
    atomicAdd(&g_deg[a.y], 1);
    atomicAdd(&g_deg[a.z], 1);
    atomicAdd(&g_deg[a.w], 1);
    atomicAdd(&g_deg[b.x], 1);
    atomicAdd(&g_deg[b.y], 1);
    atomicAdd(&g_deg[b.z], 1);
    atomicAdd(&g_deg[b.w], 1);
}

// Per-node (x4): dinv = rsqrt(indeg+1); y = x*dinv; s1 init with self-loop y.
__global__ void __launch_bounds__(256) k_node_a(const float* __restrict__ x) {
    int i = blockIdx.x * blockDim.x + threadIdx.x;
    if (i >= NN4) return;
    int4   d4 = ((const int4*)g_deg)[i];
    float4 x4 = ((const float4*)x)[i];
    float4 dv, y4;
    dv.x = rsqrtf((float)(d4.x + 1));
    dv.y = rsqrtf((float)(d4.y + 1));
    dv.z = rsqrtf((float)(d4.z + 1));
    dv.w = rsqrtf((float)(d4.w + 1));
    y4.x = x4.x * dv.x; y4.y = x4.y * dv.y;
    y4.z = x4.z * dv.z; y4.w = x4.w * dv.w;
    ((float4*)g_dinv)[i] = dv;
    ((float4*)g_y)[i]    = y4;
    ((float4*)g_s1)[i]   = y4;   // self-loop; final *dinv[c] in k_node_b
}

// Layer-1 scatter: s1[col] += y[row]  (8 edges/thread, plain loads)
__global__ void __launch_bounds__(256) k_edge_pass2(const int* __restrict__ row,
                                                    const int* __restrict__ col) {
    int idx = blockIdx.x * blockDim.x + threadIdx.x;
    if (idx >= E8) return;
    const int4* r4 = (const int4*)row;
    const int4* c4 = (const int4*)col;
    int4 ra = r4[2 * idx], rb = r4[2 * idx + 1];
    int4 ca = c4[2 * idx], cb = c4[2 * idx + 1];
    float y0 = g_y[ra.x], y1 = g_y[ra.y], y2 = g_y[ra.z], y3 = g_y[ra.w];
    float y4 = g_y[rb.x], y5 = g_y[rb.y], y6 = g_y[rb.z], y7 = g_y[rb.w];
    red_f32(&g_s1[ca.x], y0);
    red_f32(&g_s1[ca.y], y1);
    red_f32(&g_s1[ca.z], y2);
    red_f32(&g_s1[ca.w], y3);
    red_f32(&g_s1[cb.x], y4);
    red_f32(&g_s1[cb.y], y5);
    red_f32(&g_s1[cb.z], y6);
    red_f32(&g_s1[cb.w], y7);
}

// Per-node MLP (x4 nodes/thread). b1==0 fast path: z = s * (s>0 ? A+ : A-),
// with A± computed per-block (thread 0) from W1/W2 — no separate prep launch.
__global__ void __launch_bounds__(256) k_node_b(const float* __restrict__ W1,
                                                const float* __restrict__ b1,
                                                const float* __restrict__ W2) {
    __shared__ float2 s_ap, s_an;
    __shared__ int    s_bz;
    if (threadIdx.x == 0) {
        float2 ap = make_float2(0.f, 0.f), an = make_float2(0.f, 0.f);
        int bz = 1;
        #pragma unroll
        for (int j = 0; j < 16; j++) {
            if (b1[j] != 0.f) bz = 0;
            float w = W1[j];
            float w20 = W2[2 * j], w21 = W2[2 * j + 1];
            if (w > 0.f) { ap.x = fmaf(w, w20, ap.x); ap.y = fmaf(w, w21, ap.y); }
            else if (w < 0.f) { an.x = fmaf(w, w20, an.x); an.y = fmaf(w, w21, an.y); }
        }
        s_ap = ap; s_an = an; s_bz = bz;
    }
    __syncthreads();

    int i = blockIdx.x * blockDim.x + threadIdx.x;
    if (i >= NN4) return;
    float4 dv4 = ((const float4*)g_dinv)[i];
    float4 s14 = ((const float4*)g_s1)[i];

    float dv[4] = {dv4.x, dv4.y, dv4.z, dv4.w};
    float sv[4] = {dv4.x * s14.x, dv4.y * s14.y, dv4.z * s14.z, dv4.w * s14.w};
    float2 tv[4];

    if (s_bz) {
        float2 ap = s_ap, an = s_an;
        #pragma unroll
        for (int q = 0; q < 4; q++) {
            float s = sv[q];
            float2 A = (s > 0.f) ? ap : an;
            float sd = s * dv[q];
            tv[q] = make_float2(sd * A.x, sd * A.y);
        }
    } else {
        #pragma unroll
        for (int q = 0; q < 4; q++) {
            float s = sv[q];
            float z0 = 0.f, z1 = 0.f;
            #pragma unroll
            for (int j = 0; j < 16; j++) {
                float h = fmaxf(fmaf(W1[j], s, b1[j]), 0.f);
                z0 = fmaf(h, W2[2 * j], z0);
                z1 = fmaf(h, W2[2 * j + 1], z1);
            }
            tv[q] = make_float2(z0 * dv[q], z1 * dv[q]);
        }
    }
    float4 lo = make_float4(tv[0].x, tv[0].y, tv[1].x, tv[1].y);
    float4 hi = make_float4(tv[2].x, tv[2].y, tv[3].x, tv[3].y);
    ((float4*)g_t)[2 * i]        = lo;
    ((float4*)g_t)[2 * i + 1]    = hi;
    ((float4*)g_oacc)[2 * i]     = lo;   // self-loop init
    ((float4*)g_oacc)[2 * i + 1] = hi;
}

// Layer-2 scatter: oacc[col] += t[row]  (vector RED, 8 edges/thread)
__global__ void __launch_bounds__(256) k_edge_pass3(const int* __restrict__ row,
                                                    const int* __restrict__ col) {
    int idx = blockIdx.x * blockDim.x + threadIdx.x;
    if (idx >= E8) return;
    const int4* r4 = (const int4*)row;
    const int4* c4 = (const int4*)col;
    int4 ra = r4[2 * idx], rb = r4[2 * idx + 1];
    int4 ca = c4[2 * idx], cb = c4[2 * idx + 1];
    float2 t0 = g_t[ra.x], t1 = g_t[ra.y], t2 = g_t[ra.z], t3 = g_t[ra.w];
    float2 t4 = g_t[rb.x], t5 = g_t[rb.y], t6 = g_t[rb.z], t7 = g_t[rb.w];
    red_v2f32(&g_oacc[ca.x], t0);
    red_v2f32(&g_oacc[ca.y], t1);
    red_v2f32(&g_oacc[ca.z], t2);
    red_v2f32(&g_oacc[ca.w], t3);
    red_v2f32(&g_oacc[cb.x], t4);
    red_v2f32(&g_oacc[cb.y], t5);
    red_v2f32(&g_oacc[cb.z], t6);
    red_v2f32(&g_oacc[cb.w], t7);
}

// Final: scale by dinv, add b2, 2-way softmax (2 nodes/thread via float4).
// Also re-zeroes g_deg for the next call (deterministic across replays).
__global__ void __launch_bounds__(256) k_node_c(const float* __restrict__ b2,
                                                float* __restrict__ out) {
    int i = blockIdx.x * blockDim.x + threadIdx.x;   // pair index
    if (i >= N_NODES / 2) return;
    float bb0 = b2[0], bb1 = b2[1];
    float2 dv = ((const float2*)g_dinv)[i];
    float4 a  = ((const float4*)g_oacc)[i];
    float4 o;
    {
        float o0 = fmaf(dv.x, a.x, bb0);
        float o1 = fmaf(dv.x, a.y, bb1);
        float m = fmaxf(o0, o1);
        float e0 = __expf(o0 - m), e1 = __expf(o1 - m);
        float inv = __frcp_rn(e0 + e1);
        o.x = e0 * inv; o.y = e1 * inv;
    }
    {
        float o0 = fmaf(dv.y, a.z, bb0);
        float o1 = fmaf(dv.y, a.w, bb1);
        float m = fmaxf(o0, o1);
        float e0 = __expf(o0 - m), e1 = __expf(o1 - m);
        float inv = __frcp_rn(e0 + e1);
        o.z = e0 * inv; o.w = e1 * inv;
    }
    ((float4*)out)[i] = o;
    ((int2*)g_deg)[i] = make_int2(0, 0);   // zero for next call
}

extern "C" void kernel_launch(void* const* d_in, const int* in_sizes, int n_in,
                              void* d_out, int out_size) {
    const float* x   = (const float*)d_in[0];
    const int*   row = (const int*)d_in[1];            // [2, N_EDGES] int32
    const int*   col = row + N_EDGES;
    const float* W1  = (const float*)d_in[2];
    const float* b1  = (const float*)d_in[3];
    const float* W2  = (const float*)d_in[4];
    const float* b2  = (const float*)d_in[5];
    float* out = (float*)d_out;

    const int BT = 256;
    const int node4Grid = (NN4 + BT - 1) / BT;
    const int pairGrid  = (N_NODES / 2 + BT - 1) / BT;
    const int edge8Grid = (E8 + BT - 1) / BT;

    k_edge_deg<<<edge8Grid, BT>>>(col);
    k_node_a<<<node4Grid, BT>>>(x);
    k_edge_pass2<<<edge8Grid, BT>>>(row, col);
    k_node_b<<<node4Grid, BT>>>(W1, b1, W2);
    k_edge_pass3<<<edge8Grid, BT>>>(row, col);
    k_node_c<<<pairGrid, BT>>>(b2, out);
}

// round 16
// speedup vs baseline: 1.1540x; 1.0184x over previous
#include <cuda_runtime.h>
#include <cuda_bf16.h>

#define N_NODES 250000
#define N_EDGES 5000000
#define E8 (N_EDGES / 8)     // 625,000 threads for edge kernels
#define NN4 (N_NODES / 4)    // 62,500

// Scratch (device globals — no allocation allowed).
// g_deg is zero at process start (BSS) and re-zeroed at the end of every
// kernel_launch by k_node_c, so each call sees zeros. Deterministic.
__device__ int    g_deg[N_NODES];
__device__ float  g_dinv[N_NODES];
__device__ float  g_y[N_NODES];      // x[i] * dinv[i]
__device__ float  g_s1[N_NODES];     // layer-1 scatter accumulator
__device__ float2 g_t[N_NODES];      // per-node layer-2 message (z * dinv)
__device__ float2 g_oacc[N_NODES];   // layer-2 scatter accumulator

__device__ __forceinline__ void red_f32(float* p, float v) {
    asm volatile("red.global.add.f32 [%0], %1;" :: "l"(p), "f"(v) : "memory");
}
__device__ __forceinline__ void red_v2f32(float2* p, float2 v) {
    asm volatile("red.global.add.v2.f32 [%0], {%1, %2};"
                 :: "l"(p), "f"(v.x), "f"(v.y) : "memory");
}

// ---------------------------------------------------------------------------
// Degree pass: count in-degree from col (8 edges/thread).
// PDL: trigger successor immediately; idx loads are this kernel's only input.
__global__ void __launch_bounds__(256) k_edge_deg(const int* __restrict__ col) {
    cudaTriggerProgrammaticLaunchCompletion();
    int idx = blockIdx.x * blockDim.x + threadIdx.x;
    if (idx >= E8) return;
    const int4* c4 = (const int4*)col;
    int4 a = c4[2 * idx], b = c4[2 * idx + 1];
    cudaGridDependencySynchronize();   // no-op for first kernel; safe
    atomicAdd(&g_deg[a.x], 1);
    atomicAdd(&g_deg[a.y], 1);
    atomicAdd(&g_deg[a.z], 1);
    atomicAdd(&g_deg[a.w], 1);
    atomicAdd(&g_deg[b.x], 1);
    atomicAdd(&g_deg[b.y], 1);
    atomicAdd(&g_deg[b.z], 1);
    atomicAdd(&g_deg[b.w], 1);
}

// Per-node (x4): dinv = rsqrt(indeg+1); y = x*dinv; s1 init with self-loop y.
// Prologue: load x (independent of g_deg). Trigger early so pass2 can start
// streaming its 40MB of indices during this kernel.
__global__ void __launch_bounds__(256) k_node_a(const float* __restrict__ x) {
    cudaTriggerProgrammaticLaunchCompletion();
    int i = blockIdx.x * blockDim.x + threadIdx.x;
    if (i >= NN4) return;
    float4 x4 = ((const float4*)x)[i];
    cudaGridDependencySynchronize();   // wait for deg complete
    int4 d4 = ((const int4*)g_deg)[i];
    float4 dv, y4;
    dv.x = rsqrtf((float)(d4.x + 1));
    dv.y = rsqrtf((float)(d4.y + 1));
    dv.z = rsqrtf((float)(d4.z + 1));
    dv.w = rsqrtf((float)(d4.w + 1));
    y4.x = x4.x * dv.x; y4.y = x4.y * dv.y;
    y4.z = x4.z * dv.z; y4.w = x4.w * dv.w;
    ((float4*)g_dinv)[i] = dv;
    ((float4*)g_y)[i]    = y4;
    ((float4*)g_s1)[i]   = y4;   // self-loop; final *dinv[c] in k_node_b
}

// Layer-1 scatter: s1[col] += y[row]  (8 edges/thread).
// Prologue: stream 4 int4 index loads, then wait on node_a.
__global__ void __launch_bounds__(256) k_edge_pass2(const int* __restrict__ row,
                                                    const int* __restrict__ col) {
    cudaTriggerProgrammaticLaunchCompletion();
    int idx = blockIdx.x * blockDim.x + threadIdx.x;
    if (idx >= E8) return;
    const int4* r4 = (const int4*)row;
    const int4* c4 = (const int4*)col;
    int4 ra = r4[2 * idx], rb = r4[2 * idx + 1];
    int4 ca = c4[2 * idx], cb = c4[2 * idx + 1];
    cudaGridDependencySynchronize();   // wait for g_y/g_s1 ready
    float y0 = g_y[ra.x], y1 = g_y[ra.y], y2 = g_y[ra.z], y3 = g_y[ra.w];
    float y4 = g_y[rb.x], y5 = g_y[rb.y], y6 = g_y[rb.z], y7 = g_y[rb.w];
    red_f32(&g_s1[ca.x], y0);
    red_f32(&g_s1[ca.y], y1);
    red_f32(&g_s1[ca.z], y2);
    red_f32(&g_s1[ca.w], y3);
    red_f32(&g_s1[cb.x], y4);
    red_f32(&g_s1[cb.y], y5);
    red_f32(&g_s1[cb.z], y6);
    red_f32(&g_s1[cb.w], y7);
}

// Per-node MLP (x4 nodes/thread). b1==0 fast path: z = s * (s>0 ? A+ : A-).
// A± computed redundantly per-thread (broadcast loads, no sync, no serial
// thread-0 latency chain). Prologue = weight loads (independent of pass2).
__global__ void __launch_bounds__(256) k_node_b(const float* __restrict__ W1,
                                                const float* __restrict__ b1,
                                                const float* __restrict__ W2) {
    cudaTriggerProgrammaticLaunchCompletion();
    float2 ap = make_float2(0.f, 0.f), an = make_float2(0.f, 0.f);
    int bz = 1;
    #pragma unroll
    for (int j = 0; j < 16; j++) {
        if (b1[j] != 0.f) bz = 0;
        float w = W1[j];
        float w20 = W2[2 * j], w21 = W2[2 * j + 1];
        if (w > 0.f) { ap.x = fmaf(w, w20, ap.x); ap.y = fmaf(w, w21, ap.y); }
        else if (w < 0.f) { an.x = fmaf(w, w20, an.x); an.y = fmaf(w, w21, an.y); }
    }
    int i = blockIdx.x * blockDim.x + threadIdx.x;
    if (i >= NN4) return;
    cudaGridDependencySynchronize();   // wait for s1 complete
    float4 dv4 = ((const float4*)g_dinv)[i];
    float4 s14 = ((const float4*)g_s1)[i];

    float dv[4] = {dv4.x, dv4.y, dv4.z, dv4.w};
    float sv[4] = {dv4.x * s14.x, dv4.y * s14.y, dv4.z * s14.z, dv4.w * s14.w};
    float2 tv[4];

    if (bz) {
        #pragma unroll
        for (int q = 0; q < 4; q++) {
            float s = sv[q];
            float2 A = (s > 0.f) ? ap : an;
            float sd = s * dv[q];
            tv[q] = make_float2(sd * A.x, sd * A.y);
        }
    } else {
        #pragma unroll
        for (int q = 0; q < 4; q++) {
            float s = sv[q];
            float z0 = 0.f, z1 = 0.f;
            #pragma unroll
            for (int j = 0; j < 16; j++) {
                float h = fmaxf(fmaf(W1[j], s, b1[j]), 0.f);
                z0 = fmaf(h, W2[2 * j], z0);
                z1 = fmaf(h, W2[2 * j + 1], z1);
            }
            tv[q] = make_float2(z0 * dv[q], z1 * dv[q]);
        }
    }
    float4 lo = make_float4(tv[0].x, tv[0].y, tv[1].x, tv[1].y);
    float4 hi = make_float4(tv[2].x, tv[2].y, tv[3].x, tv[3].y);
    ((float4*)g_t)[2 * i]        = lo;
    ((float4*)g_t)[2 * i + 1]    = hi;
    ((float4*)g_oacc)[2 * i]     = lo;   // self-loop init
    ((float4*)g_oacc)[2 * i + 1] = hi;
}

// Layer-2 scatter: oacc[col] += t[row]  (vector RED, 8 edges/thread).
__global__ void __launch_bounds__(256) k_edge_pass3(const int* __restrict__ row,
                                                    const int* __restrict__ col) {
    cudaTriggerProgrammaticLaunchCompletion();
    int idx = blockIdx.x * blockDim.x + threadIdx.x;
    if (idx >= E8) return;
    const int4* r4 = (const int4*)row;
    const int4* c4 = (const int4*)col;
    int4 ra = r4[2 * idx], rb = r4[2 * idx + 1];
    int4 ca = c4[2 * idx], cb = c4[2 * idx + 1];
    cudaGridDependencySynchronize();   // wait for g_t/g_oacc ready
    float2 t0 = g_t[ra.x], t1 = g_t[ra.y], t2 = g_t[ra.z], t3 = g_t[ra.w];
    float2 t4 = g_t[rb.x], t5 = g_t[rb.y], t6 = g_t[rb.z], t7 = g_t[rb.w];
    red_v2f32(&g_oacc[ca.x], t0);
    red_v2f32(&g_oacc[ca.y], t1);
    red_v2f32(&g_oacc[ca.z], t2);
    red_v2f32(&g_oacc[ca.w], t3);
    red_v2f32(&g_oacc[cb.x], t4);
    red_v2f32(&g_oacc[cb.y], t5);
    red_v2f32(&g_oacc[cb.z], t6);
    red_v2f32(&g_oacc[cb.w], t7);
}

// Final: scale by dinv, add b2, 2-way softmax (2 nodes/thread via float4).
// Also re-zeroes g_deg for the next call (deterministic across replays).
__global__ void __launch_bounds__(256) k_node_c(const float* __restrict__ b2,
                                                float* __restrict__ out) {
    cudaTriggerProgrammaticLaunchCompletion();
    int i = blockIdx.x * blockDim.x + threadIdx.x;   // pair index
    if (i >= N_NODES / 2) return;
    float bb0 = b2[0], bb1 = b2[1];
    cudaGridDependencySynchronize();   // wait for oacc complete
    float2 dv = ((const float2*)g_dinv)[i];
    float4 a  = ((const float4*)g_oacc)[i];
    float4 o;
    {
        float o0 = fmaf(dv.x, a.x, bb0);
        float o1 = fmaf(dv.x, a.y, bb1);
        float m = fmaxf(o0, o1);
        float e0 = __expf(o0 - m), e1 = __expf(o1 - m);
        float inv = __frcp_rn(e0 + e1);
        o.x = e0 * inv; o.y = e1 * inv;
    }
    {
        float o0 = fmaf(dv.y, a.z, bb0);
        float o1 = fmaf(dv.y, a.w, bb1);
        float m = fmaxf(o0, o1);
        float e0 = __expf(o0 - m), e1 = __expf(o1 - m);
        float inv = __frcp_rn(e0 + e1);
        o.z = e0 * inv; o.w = e1 * inv;
    }
    ((float4*)out)[i] = o;
    ((int2*)g_deg)[i] = make_int2(0, 0);   // zero for next call
}

// ---------------------------------------------------------------------------
template <typename... Args>
static void launch_pdl(void (*kern)(Args...), int grid, int block, Args... args) {
    cudaLaunchConfig_t cfg = {};
    cfg.gridDim = dim3((unsigned)grid);
    cfg.blockDim = dim3((unsigned)block);
    cfg.dynamicSmemBytes = 0;
    cfg.stream = 0;   // legacy default stream (captured by harness)
    cudaLaunchAttribute attr[1];
    attr[0].id = cudaLaunchAttributeProgrammaticStreamSerialization;
    attr[0].val.programmaticStreamSerializationAllowed = 1;
    cfg.attrs = attr;
    cfg.numAttrs = 1;
    cudaLaunchKernelEx(&cfg, kern, args...);
}

extern "C" void kernel_launch(void* const* d_in, const int* in_sizes, int n_in,
                              void* d_out, int out_size) {
    const float* x   = (const float*)d_in[0];
    const int*   row = (const int*)d_in[1];            // [2, N_EDGES] int32
    const int*   col = row + N_EDGES;
    const float* W1  = (const float*)d_in[2];
    const float* b1  = (const float*)d_in[3];
    const float* W2  = (const float*)d_in[4];
    const float* b2  = (const float*)d_in[5];
    float* out = (float*)d_out;

    const int BT = 256;
    const int node4Grid = (NN4 + BT - 1) / BT;
    const int pairGrid  = (N_NODES / 2 + BT - 1) / BT;
    const int edge8Grid = (E8 + BT - 1) / BT;

    launch_pdl(k_edge_deg,  edge8Grid, BT, col);
    launch_pdl(k_node_a,    node4Grid, BT, x);
    launch_pdl(k_edge_pass2, edge8Grid, BT, row, col);
    launch_pdl(k_node_b,    node4Grid, BT, W1, b1, W2);
    launch_pdl(k_edge_pass3, edge8Grid, BT, row, col);
    launch_pdl(k_node_c,    pairGrid,  BT, b2, out);
}